// round 10
// baseline (speedup 1.0000x reference)
#include <cuda_runtime.h>
#include <cstddef>

namespace {
constexpr int Bsz = 512, Tsz = 1024, Hs = 64, R = 4;
constexpr int QS = 36;   // quarter stride (floats): banks q*36%32 = {0,4,8,12} -> conflict-free
constexpr int RS = 4 * QS;        // row stride (144 floats)
}

using ull = unsigned long long;

__device__ __forceinline__ void unpack2(ull v, float& lo, float& hi) {
    asm("mov.b64 {%0,%1},%2;" : "=f"(lo), "=f"(hi) : "l"(v));
}
__device__ __forceinline__ ull ffma2(ull a, ull b, ull c) {
    ull d;
    asm("fma.rn.f32x2 %0,%1,%2,%3;" : "=l"(d) : "l"(a), "l"(b), "l"(c));
    return d;
}
__device__ __forceinline__ float fast_ex2(float x) {
    float r; asm("ex2.approx.f32 %0,%1;" : "=f"(r) : "f"(x)); return r;
}
__device__ __forceinline__ float fast_rcp(float x) {
    float r; asm("rcp.approx.f32 %0,%1;" : "=f"(r) : "f"(x)); return r;
}
__device__ __forceinline__ float fsigmoid(float x) {
    return fast_rcp(1.0f + fast_ex2(-1.44269504f * x));
}
__device__ __forceinline__ float ftanh(float x) {
    float ax = fabsf(x);
    float t  = fast_ex2(-2.88539008f * ax);          // exp(-2|x|)
    float y  = (1.0f - t) * fast_rcp(1.0f + t);
    return copysignf(y, x);
}
__device__ __forceinline__ int hidx(int k) {         // k index -> padded offset
    return (k >> 4) * QS + (k & 15);
}
__device__ __forceinline__ float sum4(const float4& v) {
    return (v.x + v.y) + (v.z + v.w);
}

// ---------------------------------------------------------------------------
// Fused 2-layer GRU. Grid 128 x 768; CTA owns 4 batch rows.
// PHASE A: thread = (m = tx>>8, j = (tx&255)>>2, q = tx&3). Each thread dots
//   3 gate-rows (j, j+64, j+128) of matrix m over its 16-k quarter against 4
//   rows (m=0: Whh0.h1[s-1], m=1: Wih1.h1[s-1], m=2: Whh1.h2[s-2]).
//   NO shuffles: per-quarter partials go straight to sh_p[m][gate][r][j][q]
//   via coalesced STS (fire-and-forget; BAR.SYNC drains STS). q==0 lanes fold
//   the biases into their partial. h-buffer quarters padded to QS=36 floats
//   so the 4 per-warp broadcast addresses hit disjoint bank groups (the QS=20
//   layout of rounds 7/8 had q0/q2 and q1/q3 2-way conflicts on EVERY load).
// PHASE B: 512 combine tasks 1:1 on threads 0..511; each gate's 4 quarters
//   are read back as ONE LDS.128 and summed. L0 tasks apply the x-projection
//   (weights from smem). m=2 threads stage x[s+1]. Two barriers/step.
// ---------------------------------------------------------------------------
__global__ void __launch_bounds__(768, 1) gru_fused(
    const float* __restrict__ x,
    const float* __restrict__ W_ih0, const float* __restrict__ W_hh0,
    const float* __restrict__ b_ih0, const float* __restrict__ b_hh0,
    const float* __restrict__ W_ih1, const float* __restrict__ W_hh1,
    const float* __restrict__ b_ih1, const float* __restrict__ b_hh1,
    float* __restrict__ outp,        // (B,T,64)
    float* __restrict__ finalp)      // (B,64)
{
    __shared__ float sh_h1[2][R * RS];        // [parity][row*RS + hidx(k)]
    __shared__ float sh_h2[2][R * RS];
    __shared__ float sh_p [3][3][R][64][4];   // [matrix][gate][row][j][quarter]
    __shared__ float sh_wx[10][64];           // W_ih0 rows (9) + b_ih0 n (1)
    __shared__ float sh_x [2][R][3];          // staged x[t]

    const int tx = threadIdx.x;
    const int m  = tx >> 8;               // 0: Whh0, 1: Wih1, 2: Whh1
    const int l8 = tx & 255;
    const int j  = l8 >> 2;               // 0..63
    const int q  = l8 & 3;                // k-quarter
    const int kb = q * 16;

    // ---- phase-A weights: 3 gate-rows x 16-k quarter, packed f32x2 ----
    const float* __restrict__ Wm = (m == 0) ? W_hh0 : (m == 1) ? W_ih1 : W_hh1;
    ull w2[24];
    const ull* __restrict__ Wll = reinterpret_cast<const ull*>(Wm);
#pragma unroll
    for (int g3 = 0; g3 < 3; g3++) {
        const int g = j + g3 * 64;
#pragma unroll
        for (int kk = 0; kk < 8; kk++)
            w2[g3 * 8 + kk] = Wll[(g * 64 + kb) / 2 + kk];
    }

    // biases folded by the q==0 lane only (zero for other quarters)
    float b0q = 0.f, b1q = 0.f, b2q = 0.f;
    if (q == 0) {
        if (m == 0) {
            b0q = b_ih0[j]       + b_hh0[j];
            b1q = b_ih0[j + 64]  + b_hh0[j + 64];
            b2q = b_hh0[j + 128];                // recurrent n (inside r*)
        } else if (m == 1) {
            b0q = b_ih1[j]       + b_hh1[j];
            b1q = b_ih1[j + 64]  + b_hh1[j + 64];
            b2q = b_ih1[j + 128];                // input n
        } else {
            b2q = b_hh1[j + 128];                // recurrent n
        }
    }

    // ---- phase-B task (threads 0..511): (L = tx>>8, rB, jB) ----
    const int L  = tx >> 8;
    const int rB = (tx >> 6) & 3;
    const int jB = tx & 63;

    // x staging: m==2 threads 0..11
    const int  sx  = tx - 512;
    const bool xst = (m == 2) && (sx < 12);
    const int  xr  = xst ? sx / 3 : 0, xc = xst ? sx % 3 : 0;
    const int row4 = blockIdx.x * 4;

    // ---- init ----
    for (int i = tx; i < 2 * R * RS; i += 768) {
        reinterpret_cast<float*>(sh_h1)[i] = 0.f;
        reinterpret_cast<float*>(sh_h2)[i] = 0.f;
    }
    for (int i = tx; i < 640; i += 768) {
        const int rw = i >> 6, cl = i & 63;
        sh_wx[rw][cl] = (rw < 9)
            ? W_ih0[((rw / 3) * 64 + cl) * 3 + (rw % 3)]
            : b_ih0[cl + 128];
    }
    if (xst)
        sh_x[0][xr][xc] = __ldg(&x[((size_t)(row4 + xr) * Tsz) * 3 + xc]);
    __syncthreads();

    for (int s = 0; s <= Tsz; s++) {
        const int par = s & 1;

        // ===================== PHASE A: dots (pure stream) ===============
        const float* __restrict__ hsrc =
            (m == 2) ? &sh_h2[par][0] : &sh_h1[par][0];
#pragma unroll
        for (int r = 0; r < R; r++) {
            const ulonglong2* __restrict__ hb =
                reinterpret_cast<const ulonglong2*>(hsrc + r * RS + q * QS);
            ull a0 = 0ull, a1 = 0ull, a2 = 0ull;
#pragma unroll
            for (int i = 0; i < 4; i++) {
                const ulonglong2 h4 = hb[i];               // LDS.128, 4 bank-disjoint addrs
                a0 = ffma2(h4.x, w2[2 * i],          a0);
                a0 = ffma2(h4.y, w2[2 * i + 1],      a0);
                a1 = ffma2(h4.x, w2[8 + 2 * i],      a1);
                a1 = ffma2(h4.y, w2[8 + 2 * i + 1],  a1);
                a2 = ffma2(h4.x, w2[16 + 2 * i],     a2);
                a2 = ffma2(h4.y, w2[16 + 2 * i + 1], a2);
            }
            float l, h;
            unpack2(a0, l, h); sh_p[m][0][r][j][q] = (l + h) + b0q;
            unpack2(a1, l, h); sh_p[m][1][r][j][q] = (l + h) + b1q;
            unpack2(a2, l, h); sh_p[m][2][r][j][q] = (l + h) + b2q;
        }
        __syncthreads();                     // drains the STS above

        // ===================== PHASE B: combines ==========================
        if (m < 2) {                          // 512 tasks, 1:1
            if (L == 0) {
                if (s < Tsz) {                // h1[s]
                    const float pr = sum4(*reinterpret_cast<const float4*>(
                        &sh_p[0][0][rB][jB][0]));
                    const float pz = sum4(*reinterpret_cast<const float4*>(
                        &sh_p[0][1][rB][jB][0]));
                    const float pn = sum4(*reinterpret_cast<const float4*>(
                        &sh_p[0][2][rB][jB][0]));
                    const float x0 = sh_x[par][rB][0];
                    const float x1 = sh_x[par][rB][1];
                    const float x2 = sh_x[par][rB][2];
                    const float ar = pr
                        + fmaf(x2, sh_wx[2][jB],
                          fmaf(x1, sh_wx[1][jB], x0 * sh_wx[0][jB]));
                    const float az = pz
                        + fmaf(x2, sh_wx[5][jB],
                          fmaf(x1, sh_wx[4][jB], x0 * sh_wx[3][jB]));
                    const float xan = sh_wx[9][jB]
                        + fmaf(x2, sh_wx[8][jB],
                          fmaf(x1, sh_wx[7][jB], x0 * sh_wx[6][jB]));
                    const float rr = fsigmoid(ar);
                    const float zz = fsigmoid(az);
                    const float nn = ftanh(fmaf(rr, pn, xan));
                    const float hp = sh_h1[par][rB * RS + hidx(jB)];
                    sh_h1[par ^ 1][rB * RS + hidx(jB)] = fmaf(zz, hp - nn, nn);
                }
            } else {
                if (s >= 1) {                 // h2[s-1] -> output
                    const int tau = s - 1;
                    const float ar = sum4(*reinterpret_cast<const float4*>(
                                        &sh_p[1][0][rB][jB][0]))
                                   + sum4(*reinterpret_cast<const float4*>(
                                        &sh_p[2][0][rB][jB][0]));
                    const float az = sum4(*reinterpret_cast<const float4*>(
                                        &sh_p[1][1][rB][jB][0]))
                                   + sum4(*reinterpret_cast<const float4*>(
                                        &sh_p[2][1][rB][jB][0]));
                    const float xn = sum4(*reinterpret_cast<const float4*>(
                                        &sh_p[1][2][rB][jB][0]));
                    const float hn_ = sum4(*reinterpret_cast<const float4*>(
                                        &sh_p[2][2][rB][jB][0]));
                    const float rr = fsigmoid(ar);
                    const float zz = fsigmoid(az);
                    const float nn = ftanh(fmaf(rr, hn_, xn));
                    const float hp = sh_h2[par][rB * RS + hidx(jB)];
                    const float hv = fmaf(zz, hp - nn, nn);
                    sh_h2[par ^ 1][rB * RS + hidx(jB)] = hv;
                    outp[((size_t)(row4 + rB) * Tsz + tau) * Hs + jB] = hv;
                    if (tau == Tsz - 1)
                        finalp[(row4 + rB) * Hs + jB] = hv;
                }
            }
        } else if (xst && s + 1 < Tsz) {
            // stage x[s+1] into parity (s+1)&1
            sh_x[par ^ 1][xr][xc] =
                __ldg(&x[((size_t)(row4 + xr) * Tsz + (s + 1)) * 3 + xc]);
        }
        __syncthreads();
    }
}

// ---------------------------------------------------------------------------
extern "C" void kernel_launch(void* const* d_in, const int* in_sizes, int n_in,
                              void* d_out, int out_size)
{
    (void)in_sizes; (void)n_in; (void)out_size;
    const float* x     = (const float*)d_in[0];
    const float* W_ih0 = (const float*)d_in[1];
    const float* W_hh0 = (const float*)d_in[2];
    const float* b_ih0 = (const float*)d_in[3];
    const float* b_hh0 = (const float*)d_in[4];
    const float* W_ih1 = (const float*)d_in[5];
    const float* W_hh1 = (const float*)d_in[6];
    const float* b_ih1 = (const float*)d_in[7];
    const float* b_hh1 = (const float*)d_in[8];

    float* out    = (float*)d_out;
    float* finalh = out + (size_t)Bsz * Tsz * Hs;

    gru_fused<<<128, 768>>>(x, W_ih0, W_hh0, b_ih0, b_hh0,
                            W_ih1, W_hh1, b_ih1, b_hh1, out, finalh);
}